// round 11
// baseline (speedup 1.0000x reference)
#include <cuda_runtime.h>
#include <cuda_bf16.h>
#include <mma.h>
#include <cstddef>
#include <cstdint>

using namespace nvcuda;
typedef __nv_bfloat16 bf16;

#define B_    4
#define NSEQ  2048
#define CD    256
#define ICH   128
#define M2    4096                    // 2*NSEQ
#define LIN_ELEMS (B_*NSEQ*CD)        // 2,097,152
#define BSTRIDE   (NSEQ*CD)           // 524,288 per batch
#define NSPLIT    32                  // K=4096 -> 128 per block

// intermediates (bf16)
__device__ bf16 h_g    [LIN_ELEMS];
__device__ bf16 h_g2   [LIN_ELEMS];
__device__ bf16 h_theta[LIN_ELEMS];
__device__ bf16 h_phi  [LIN_ELEMS];
__device__ bf16 h_Spart[2*B_*NSPLIT*ICH*ICH];     // bf16 split-K partials (8 MB)
__device__ bf16 h_S    [2*B_*ICH*ICH];            // scaled by 1/4096
__device__ bf16 h_naT  [LIN_ELEMS];
__device__ bf16 h_ndT  [LIN_ELEMS];
__device__ int  d_cnt  [2*B_];                    // split-K arrival counters (self-reset)

typedef wmma::fragment<wmma::matrix_a, 16, 16, 16, bf16, wmma::row_major> FA_R;
typedef wmma::fragment<wmma::matrix_a, 16, 16, 16, bf16, wmma::col_major> FA_C;
typedef wmma::fragment<wmma::matrix_b, 16, 16, 16, bf16, wmma::row_major> FB_R;
typedef wmma::fragment<wmma::matrix_b, 16, 16, 16, bf16, wmma::col_major> FB_C;
typedef wmma::fragment<wmma::accumulator, 16, 16, 16, float>              FACC;

// ---- cp.async helpers -----------------------------------------------------
__device__ __forceinline__ void cp16(void* s, const void* g) {
    uint32_t sa = (uint32_t)__cvta_generic_to_shared(s);
    asm volatile("cp.async.cg.shared.global [%0], [%1], 16;\n" :: "r"(sa), "l"(g));
}
__device__ __forceinline__ void cp_commit() { asm volatile("cp.async.commit_group;\n"); }
template <int N>
__device__ __forceinline__ void cp_wait() { asm volatile("cp.async.wait_group %0;\n" :: "n"(N)); }

// Row-slab: [128 rows][40 (=32 K + 8 pad)] bf16
#define PAD_H  40
#define SLAB_H (128*PAD_H)
// K-slab (out_small): [32 K][136 (=128 + 8 pad)] bf16
#define PAD2_H  136
#define SLAB2_H (32*PAD2_H)

// 256 threads copy 128x32 bf16 tile (rows, leading dim ldg)
__device__ __forceinline__ void load_slab_h(bf16* dst, const bf16* src, size_t ldg,
                                            int k0, int t)
{
    const int row = t >> 1, c0 = (t & 1) * 16;
    const bf16* g = src + (size_t)row * ldg + k0 + c0;
    bf16* s = dst + row * PAD_H + c0;
    cp16(s, g); cp16(s + 8, g + 8);
}

// 256 threads copy 32x128 bf16 tile (K-major rows, leading dim ldg)
__device__ __forceinline__ void load_slab2_h(bf16* dst, const bf16* src, size_t ldg,
                                             int k0, int t)
{
    const int kk = t >> 3, c0 = (t & 7) * 16;
    const bf16* g = src + (size_t)(k0 + kk) * ldg + c0;
    bf16* s = dst + kk * PAD2_H + c0;
    cp16(s, g); cp16(s + 8, g + 8);
}

// fp32 path: LDG 16 floats/thread for a 128x32 slab (row stride CD)
__device__ __forceinline__ void ldg_slab_f(float4 (&r)[4], const float* src, int k0, int t)
{
    const int row = t >> 1, c0 = (t & 1) * 16;
    const float* g = src + (size_t)row * CD + k0 + c0;
    r[0] = *(const float4*)(g);
    r[1] = *(const float4*)(g + 4);
    r[2] = *(const float4*)(g + 8);
    r[3] = *(const float4*)(g + 12);
}
__device__ __forceinline__ void sts_slab_cvt(bf16* dst, const float4 (&r)[4], int t)
{
    const int row = t >> 1, c0 = (t & 1) * 16;
    bf16* s = dst + row * PAD_H + c0;
    uint4 o0, o1;
    __nv_bfloat162* p0 = (__nv_bfloat162*)&o0;
    __nv_bfloat162* p1 = (__nv_bfloat162*)&o1;
    p0[0] = __floats2bfloat162_rn(r[0].x, r[0].y);
    p0[1] = __floats2bfloat162_rn(r[0].z, r[0].w);
    p0[2] = __floats2bfloat162_rn(r[1].x, r[1].y);
    p0[3] = __floats2bfloat162_rn(r[1].z, r[1].w);
    p1[0] = __floats2bfloat162_rn(r[2].x, r[2].y);
    p1[1] = __floats2bfloat162_rn(r[2].z, r[2].w);
    p1[2] = __floats2bfloat162_rn(r[3].x, r[3].y);
    p1[3] = __floats2bfloat162_rn(r[3].z, r[3].w);
    *(uint4*)(s)     = o0;
    *(uint4*)(s + 8) = o1;
}

// MMA consume of one 32-K slab pair
__device__ __forceinline__ void consume_slab(const bf16* Ab, const bf16* Bb,
                                             FACC (&acc)[2][4], int mwl, int nwl)
{
#pragma unroll
    for (int ks = 0; ks < 2; ks++) {
        const int kk = ks * 16;
        FA_R a[2];
        FB_C b[4];
#pragma unroll
        for (int i = 0; i < 2; i++)
            wmma::load_matrix_sync(a[i], Ab + (mwl + 16 * i) * PAD_H + kk, PAD_H);
#pragma unroll
        for (int j = 0; j < 4; j++)
            wmma::load_matrix_sync(b[j], Bb + (nwl + 16 * j) * PAD_H + kk, PAD_H);
#pragma unroll
        for (int i = 0; i < 2; i++)
#pragma unroll
            for (int j = 0; j < 4; j++) wmma::mma_sync(acc[i][j], a[i], b[j], acc[i][j]);
    }
}

// Depth-2 mainloop (bf16 X + bf16 W, cp.async both)
__device__ __forceinline__ void mainloop_h(
    const bf16* Xt, size_t ldx, const bf16* Wt, size_t ldw, int NT,
    bf16* As, bf16* Bs, FACC (&acc)[2][4], int tid, int mwl, int nwl)
{
    load_slab_h(As, Xt, ldx, 0, tid);
    load_slab_h(Bs, Wt, ldw, 0, tid);
    cp_commit();
    for (int kt = 0; kt < NT; kt++) {
        const int cur = kt & 1;
        if (kt + 1 < NT) {
            load_slab_h(As + ((kt + 1) & 1) * SLAB_H, Xt, ldx, (kt + 1) * 32, tid);
            load_slab_h(Bs + ((kt + 1) & 1) * SLAB_H, Wt, ldw, (kt + 1) * 32, tid);
            cp_commit();
            cp_wait<1>();
        } else {
            cp_wait<0>();
        }
        __syncthreads();
        consume_slab(As + cur * SLAB_H, Bs + cur * SLAB_H, acc, mwl, nwl);
        __syncthreads();
    }
}

// lin4 mainloop: BOTH X and W fp32, LDG->cvt->STS register double-buffer. NT=8.
__device__ __forceinline__ void mainloop_f32xw(
    const float* Xt, const float* Wt, bf16* As, bf16* Bs,
    FACC (&acc)[2][4], int tid, int mwl, int nwl)
{
    const int NT = CD / 32;
    float4 rx[4], rw[4];
    ldg_slab_f(rx, Xt, 0, tid);
    ldg_slab_f(rw, Wt, 0, tid);
    for (int kt = 0; kt < NT; kt++) {
        const int cur = kt & 1;
        sts_slab_cvt(As + cur * SLAB_H, rx, tid);
        sts_slab_cvt(Bs + cur * SLAB_H, rw, tid);
        if (kt + 1 < NT) {
            ldg_slab_f(rx, Xt, (kt + 1) * 32, tid);   // overlaps consume
            ldg_slab_f(rw, Wt, (kt + 1) * 32, tid);
        }
        __syncthreads();
        consume_slab(As + cur * SLAB_H, Bs + cur * SLAB_H, acc, mwl, nwl);
        __syncthreads();
    }
}

// lin2 mainloop: X bf16 via cp.async, W fp32 LDG->cvt->STS. NT=8.
__device__ __forceinline__ void mainloop_hx_fw(
    const bf16* Xt, const float* Wt, bf16* As, bf16* Bs,
    FACC (&acc)[2][4], int tid, int mwl, int nwl)
{
    const int NT = CD / 32;
    float4 rw[4];
    load_slab_h(As, Xt, CD, 0, tid);
    cp_commit();
    ldg_slab_f(rw, Wt, 0, tid);
    for (int kt = 0; kt < NT; kt++) {
        const int cur = kt & 1;
        sts_slab_cvt(Bs + cur * SLAB_H, rw, tid);
        if (kt + 1 < NT) {
            load_slab_h(As + ((kt + 1) & 1) * SLAB_H, Xt, CD, (kt + 1) * 32, tid);
            cp_commit();
            ldg_slab_f(rw, Wt, (kt + 1) * 32, tid);
            cp_wait<1>();
        } else {
            cp_wait<0>();
        }
        __syncthreads();
        consume_slab(As + cur * SLAB_H, Bs + cur * SLAB_H, acc, mwl, nwl);
        __syncthreads();
    }
}

// ---------------------------------------------------------------------------
// Front linears: Y = X_fp32 @ W_fp32^T + bias, bf16 out. grid (64,2,4)
// Weights converted on the fly (no cvt kernel).
// ---------------------------------------------------------------------------
__global__ __launch_bounds__(256, 2) void lin4_tc(
    const float* __restrict__ Xdet, const float* __restrict__ Xaim,
    const float* __restrict__ Wg,  const float* __restrict__ Wg2,
    const float* __restrict__ Wth, const float* __restrict__ Wph,
    const float* __restrict__ b0, const float* __restrict__ b1,
    const float* __restrict__ b2, const float* __restrict__ b3)
{
    extern __shared__ bf16 smem[];
    __shared__ float patch[8][16][20];
    const int z = blockIdx.z;
    const float* X; const float* W; const float* bias; bf16* Y;
    if      (z == 0) { X = Xdet; W = Wg;  bias = b0; Y = h_g;     }
    else if (z == 1) { X = Xaim; W = Wg2; bias = b1; Y = h_g2;    }
    else if (z == 2) { X = Xaim; W = Wth; bias = b2; Y = h_theta; }
    else             { X = Xdet; W = Wph; bias = b3; Y = h_phi;   }

    const int tid = threadIdx.x, wid = tid >> 5, lane = tid & 31;
    const int wm = wid & 3, wn = wid >> 2;

    FACC acc[2][4];
#pragma unroll
    for (int i = 0; i < 2; i++)
#pragma unroll
        for (int j = 0; j < 4; j++) wmma::fill_fragment(acc[i][j], 0.0f);

    mainloop_f32xw(X + (size_t)(blockIdx.x * 128) * CD,
                   W + (size_t)(blockIdx.y * 128) * CD,
                   smem, smem + 2 * SLAB_H, acc, tid, wm * 32, wn * 64);

    const int m0 = blockIdx.x * 128 + wm * 32;
    const int n0 = blockIdx.y * 128 + wn * 64;
    const int pr = lane & 15, pc = (lane >> 4) * 8;
#pragma unroll
    for (int i = 0; i < 2; i++)
#pragma unroll
        for (int j = 0; j < 4; j++) {
            wmma::store_matrix_sync(&patch[wid][0][0], acc[i][j], 20, wmma::mem_row_major);
            __syncwarp();
            const int m = m0 + 16 * i + pr;
            const int nb = n0 + 16 * j + pc;
            uint4 o;
            __nv_bfloat162* op = (__nv_bfloat162*)&o;
#pragma unroll
            for (int t = 0; t < 4; t++)
                op[t] = __floats2bfloat162_rn(patch[wid][pr][pc + 2*t]     + bias[nb + 2*t],
                                              patch[wid][pr][pc + 2*t + 1] + bias[nb + 2*t + 1]);
            *(uint4*)&Y[(size_t)m * CD + nb] = o;
            __syncwarp();
        }
}

// ---------------------------------------------------------------------------
// Split-K partials + in-kernel deterministic fixup.
// type 0: S1 = Ph @ Gr^T ; 1: S2 = Th @ A2^T.  grid (NSPLIT=32, 2, B_).
// Last-arriving block per (type,b) sums all 32 partials (fixed order) -> h_S,
// then resets its counter (graph-replay safe).
// ---------------------------------------------------------------------------
__global__ __launch_bounds__(256, 2) void s_partial_tc()
{
    extern __shared__ bf16 smem[];
    __shared__ float patch[8][16][20];
    __shared__ int isLast;
    const int split = blockIdx.x, type = blockIdx.y, b = blockIdx.z;
    const bf16* A  = (type ? h_theta : h_phi) + (size_t)b * BSTRIDE;
    const bf16* Bm = (type ? h_g2   : h_g  ) + (size_t)b * BSTRIDE;
    const int kbase = split * (M2 / NSPLIT);
    const int tid = threadIdx.x, wid = tid >> 5, lane = tid & 31;
    const int wm = wid & 3, wn = wid >> 2;
    const int mat = type * B_ + b;

    FACC acc[2][4];
#pragma unroll
    for (int i = 0; i < 2; i++)
#pragma unroll
        for (int j = 0; j < 4; j++) wmma::fill_fragment(acc[i][j], 0.0f);

    mainloop_h(A + kbase, M2, Bm + kbase, M2, (M2 / NSPLIT) / 32,
               smem, smem + 2 * SLAB_H, acc, tid, wm * 32, wn * 64);

    bf16* out = h_Spart + ((size_t)(mat * NSPLIT + split)) * (ICH * ICH);
    const int pr = lane & 15, pc = (lane >> 4) * 8;
#pragma unroll
    for (int i = 0; i < 2; i++)
#pragma unroll
        for (int j = 0; j < 4; j++) {
            wmma::store_matrix_sync(&patch[wid][0][0], acc[i][j], 20, wmma::mem_row_major);
            __syncwarp();
            const int r = wm * 32 + 16 * i + pr;
            const int c = wn * 64 + 16 * j + pc;
            uint4 o;
            __nv_bfloat162* op = (__nv_bfloat162*)&o;
#pragma unroll
            for (int t = 0; t < 4; t++)
                op[t] = __floats2bfloat162_rn(patch[wid][pr][pc + 2*t], patch[wid][pr][pc + 2*t + 1]);
            *(uint4*)&out[(size_t)r * ICH + c] = o;
            __syncwarp();
        }

    // split-K fixup: last block per (type,b) reduces all partials
    __threadfence();
    if (tid == 0) {
        int old = atomicAdd(&d_cnt[mat], 1);
        isLast = (old == NSPLIT - 1);
    }
    __syncthreads();
    if (!isLast) return;
    __threadfence();
    const bf16* base = h_Spart + (size_t)mat * NSPLIT * (ICH * ICH);
    for (int e = tid * 2; e < ICH * ICH; e += 512) {
        float s0 = 0.0f, s1 = 0.0f;
#pragma unroll
        for (int sp = 0; sp < NSPLIT; sp++) {
            __nv_bfloat162 v = *(const __nv_bfloat162*)(base + (size_t)sp * (ICH * ICH) + e);
            float2 f = __bfloat1622float2(v);
            s0 += f.x; s1 += f.y;
        }
        *(__nv_bfloat162*)&h_S[(size_t)mat * (ICH * ICH) + e] =
            __floats2bfloat162_rn(s0 * (1.0f / 4096.0f), s1 * (1.0f / 4096.0f));
    }
    __syncthreads();
    if (tid == 0) d_cnt[mat] = 0;     // self-reset for next graph replay
}

// ---------------------------------------------------------------------------
// C[i,p] = sum_k S[k,i] * Tm[k,p]  (S^T @ Tm), bf16 in/out. grid (32, 2, B_)
// ---------------------------------------------------------------------------
__global__ __launch_bounds__(256, 2) void out_small_tc()
{
    extern __shared__ bf16 smem[];
    bf16* Ss = smem;
    bf16* Ts = smem + 2 * SLAB2_H;
    __shared__ float patch[8][16][20];
    const int p0 = blockIdx.x * 128, type = blockIdx.y, b = blockIdx.z;
    const bf16* S  = h_S + (size_t)(type * B_ + b) * (ICH * ICH);
    const bf16* Tm = (type ? h_phi : h_theta) + (size_t)b * BSTRIDE;
    bf16* Y = (type ? h_ndT : h_naT) + (size_t)b * BSTRIDE;
    const int tid = threadIdx.x, wid = tid >> 5, lane = tid & 31;
    const int wm = wid & 3, wn = wid >> 2;
    const int iw = wm * 32, pwl = wn * 64;

    FACC acc[2][4];
#pragma unroll
    for (int i = 0; i < 2; i++)
#pragma unroll
        for (int j = 0; j < 4; j++) wmma::fill_fragment(acc[i][j], 0.0f);

    load_slab2_h(Ss, S, ICH, 0, tid);
    load_slab2_h(Ts, Tm + p0, M2, 0, tid);
    cp_commit();
    const int NT = ICH / 32;            // 4
#pragma unroll
    for (int kt = 0; kt < NT; kt++) {
        const int cur = kt & 1;
        if (kt + 1 < NT) {
            load_slab2_h(Ss + ((kt + 1) & 1) * SLAB2_H, S, ICH, (kt + 1) * 32, tid);
            load_slab2_h(Ts + ((kt + 1) & 1) * SLAB2_H, Tm + p0, M2, (kt + 1) * 32, tid);
            cp_commit();
            cp_wait<1>();
        } else {
            cp_wait<0>();
        }
        __syncthreads();
        const bf16* Sb = Ss + cur * SLAB2_H;
        const bf16* Tb = Ts + cur * SLAB2_H;
#pragma unroll
        for (int ks = 0; ks < 2; ks++) {
            const int kk = ks * 16;
            FA_C a[2];
            FB_R bf[4];
#pragma unroll
            for (int i = 0; i < 2; i++)
                wmma::load_matrix_sync(a[i], Sb + kk * PAD2_H + iw + 16 * i, PAD2_H);
#pragma unroll
            for (int j = 0; j < 4; j++)
                wmma::load_matrix_sync(bf[j], Tb + kk * PAD2_H + pwl + 16 * j, PAD2_H);
#pragma unroll
            for (int i = 0; i < 2; i++)
#pragma unroll
                for (int j = 0; j < 4; j++) wmma::mma_sync(acc[i][j], a[i], bf[j], acc[i][j]);
        }
        __syncthreads();
    }
    const int pr = lane & 15, pc = (lane >> 4) * 8;
#pragma unroll
    for (int i = 0; i < 2; i++)
#pragma unroll
        for (int j = 0; j < 4; j++) {
            wmma::store_matrix_sync(&patch[wid][0][0], acc[i][j], 20, wmma::mem_row_major);
            __syncwarp();
            const int r = iw + 16 * i + pr;
            const int c = p0 + pwl + 16 * j + pc;
            uint4 o;
            __nv_bfloat162* op = (__nv_bfloat162*)&o;
#pragma unroll
            for (int t = 0; t < 4; t++)
                op[t] = __floats2bfloat162_rn(patch[wid][pr][pc + 2*t], patch[wid][pr][pc + 2*t + 1]);
            *(uint4*)&Y[(size_t)r * M2 + c] = o;
            __syncwarp();
        }
}

// ---------------------------------------------------------------------------
// Final linears + residual (fp32 out), W fp32 on the fly. grid (64, 2, 2)
// ---------------------------------------------------------------------------
__global__ __launch_bounds__(256, 2) void lin2_tc(
    const float* __restrict__ Qw, const float* __restrict__ Qb, const float* __restrict__ det,
    const float* __restrict__ Ww, const float* __restrict__ Wb, const float* __restrict__ aim,
    float* __restrict__ out_det, float* __restrict__ out_aim)
{
    extern __shared__ bf16 smem[];
    __shared__ float patch[8][16][20];
    const int z = blockIdx.z;
    const bf16* X = z ? h_naT : h_ndT;
    const float* W = z ? Ww : Qw;
    const float* bias = z ? Wb : Qb;
    const float* res  = z ? aim : det;
    float* Y = z ? out_aim : out_det;

    const int tid = threadIdx.x, wid = tid >> 5, lane = tid & 31;
    const int wm = wid & 3, wn = wid >> 2;

    FACC acc[2][4];
#pragma unroll
    for (int i = 0; i < 2; i++)
#pragma unroll
        for (int j = 0; j < 4; j++) wmma::fill_fragment(acc[i][j], 0.0f);

    mainloop_hx_fw(X + (size_t)(blockIdx.x * 128) * CD,
                   W + (size_t)(blockIdx.y * 128) * CD,
                   smem, smem + 2 * SLAB_H, acc, tid, wm * 32, wn * 64);

    const int m0 = blockIdx.x * 128 + wm * 32;
    const int n0 = blockIdx.y * 128 + wn * 64;
    const int pr = lane & 15, pc = (lane >> 4) * 8;
#pragma unroll
    for (int i = 0; i < 2; i++)
#pragma unroll
        for (int j = 0; j < 4; j++) {
            wmma::store_matrix_sync(&patch[wid][0][0], acc[i][j], 20, wmma::mem_row_major);
            __syncwarp();
            const int m = m0 + 16 * i + pr;
            const int nb = n0 + 16 * j + pc;
            const float* rrow = &res[(size_t)m * CD + nb];
            float r[8];
#pragma unroll
            for (int t = 0; t < 8; t++)
                r[t] = patch[wid][pr][pc + t] + bias[nb + t] + rrow[t];
            float* row = &Y[(size_t)m * CD + nb];
            *(float4*)(row)     = make_float4(r[0], r[1], r[2], r[3]);
            *(float4*)(row + 4) = make_float4(r[4], r[5], r[6], r[7]);
            __syncwarp();
        }
}

// ---------------------------------------------------------------------------
extern "C" void kernel_launch(void* const* d_in, const int* in_sizes, int n_in,
                              void* d_out, int out_size)
{
    const float* detect = (const float*)d_in[0];
    const float* aim    = (const float*)d_in[1];
    const float* g_w  = (const float*)d_in[2];  const float* g_b  = (const float*)d_in[3];
    const float* g2_w = (const float*)d_in[4];  const float* g2_b = (const float*)d_in[5];
    const float* th_w = (const float*)d_in[6];  const float* th_b = (const float*)d_in[7];
    const float* ph_w = (const float*)d_in[8];  const float* ph_b = (const float*)d_in[9];
    const float* W_w  = (const float*)d_in[10]; const float* W_b  = (const float*)d_in[11];
    const float* Q_w  = (const float*)d_in[12]; const float* Q_b  = (const float*)d_in[13];

    float* out_det = (float*)d_out;
    float* out_aim = out_det + (size_t)B_ * NSEQ * CD;

    const int smemLin = 4 * SLAB_H * (int)sizeof(bf16);    // 40960
    const int smemOut = 4 * SLAB2_H * (int)sizeof(bf16);   // 34816
    cudaFuncSetAttribute(lin4_tc,      cudaFuncAttributeMaxDynamicSharedMemorySize, smemLin);
    cudaFuncSetAttribute(s_partial_tc, cudaFuncAttributeMaxDynamicSharedMemorySize, smemLin);
    cudaFuncSetAttribute(out_small_tc, cudaFuncAttributeMaxDynamicSharedMemorySize, smemOut);
    cudaFuncSetAttribute(lin2_tc,      cudaFuncAttributeMaxDynamicSharedMemorySize, smemLin);

    // Stage 1: four front linears (fp32 X AND W converted on the fly)
    lin4_tc<<<dim3(64, 2, 4), 256, smemLin>>>(
        detect, aim, g_w, g2_w, th_w, ph_w, g_b, g2_b, th_b, ph_b);

    // Stage 2: S1/S2 split-K + in-kernel fixup (writes h_S)
    s_partial_tc<<<dim3(NSPLIT, 2, B_), 256, smemLin>>>();

    // Stage 3: naT/ndT (bf16)
    out_small_tc<<<dim3(M2 / 128, 2, B_), 256, smemOut>>>();

    // Stage 4: final linears + residuals (fp32 out, W on the fly)
    lin2_tc<<<dim3(64, 2, 2), 256, smemLin>>>(
        Q_w, Q_b, detect, W_w, W_b, aim, out_det, out_aim);
}

// round 12
// speedup vs baseline: 1.2260x; 1.2260x over previous
#include <cuda_runtime.h>
#include <cuda_bf16.h>
#include <mma.h>
#include <cstddef>
#include <cstdint>

using namespace nvcuda;
typedef __nv_bfloat16 bf16;

#define B_    4
#define NSEQ  2048
#define CD    256
#define ICH   128
#define M2    4096                    // 2*NSEQ
#define LIN_ELEMS (B_*NSEQ*CD)        // 2,097,152
#define BSTRIDE   (NSEQ*CD)           // 524,288 per batch
#define NSPLIT    32                  // K=4096 -> 128 per block

// bf16 weights
__device__ bf16 h_wg [CD*CD];
__device__ bf16 h_wg2[CD*CD];
__device__ bf16 h_wth[CD*CD];
__device__ bf16 h_wph[CD*CD];
__device__ bf16 h_wW [CD*CD];
__device__ bf16 h_wQ [CD*CD];
// intermediates (bf16)
__device__ bf16 h_g    [LIN_ELEMS];
__device__ bf16 h_g2   [LIN_ELEMS];
__device__ bf16 h_theta[LIN_ELEMS];
__device__ bf16 h_phi  [LIN_ELEMS];
__device__ bf16 h_Spart[2*B_*NSPLIT*ICH*ICH];
__device__ bf16 h_S    [2*B_*ICH*ICH];
__device__ bf16 h_naT  [LIN_ELEMS];
__device__ bf16 h_ndT  [LIN_ELEMS];
// stage completion counters (zero-init; self-reset each run)
__device__ int g_cnt[6];

// Stage block counts / bid ranges
#define N_CVT   192
#define N_LIN4  512
#define N_SPART 256
#define N_RED   256
#define N_OUT   256
#define N_LIN2  256
#define B0_CVT   0
#define B0_LIN4  (B0_CVT  + N_CVT)    // 192
#define B0_SPART (B0_LIN4 + N_LIN4)   // 704
#define B0_RED   (B0_SPART+ N_SPART)  // 960
#define B0_OUT   (B0_RED  + N_RED)    // 1216
#define B0_LIN2  (B0_OUT  + N_OUT)    // 1472
#define N_TOTAL  (B0_LIN2 + N_LIN2)   // 1728

typedef wmma::fragment<wmma::matrix_a, 16, 16, 16, bf16, wmma::row_major> FA_R;
typedef wmma::fragment<wmma::matrix_a, 16, 16, 16, bf16, wmma::col_major> FA_C;
typedef wmma::fragment<wmma::matrix_b, 16, 16, 16, bf16, wmma::row_major> FB_R;
typedef wmma::fragment<wmma::matrix_b, 16, 16, 16, bf16, wmma::col_major> FB_C;
typedef wmma::fragment<wmma::accumulator, 16, 16, 16, float>              FACC;

// ---- cp.async helpers -----------------------------------------------------
__device__ __forceinline__ void cp16(void* s, const void* g) {
    uint32_t sa = (uint32_t)__cvta_generic_to_shared(s);
    asm volatile("cp.async.cg.shared.global [%0], [%1], 16;\n" :: "r"(sa), "l"(g));
}
__device__ __forceinline__ void cp_commit() { asm volatile("cp.async.commit_group;\n"); }
template <int N>
__device__ __forceinline__ void cp_wait() { asm volatile("cp.async.wait_group %0;\n" :: "n"(N)); }

#define PAD_H  40
#define SLAB_H (128*PAD_H)
#define PAD2_H  136
#define SLAB2_H (32*PAD2_H)

__device__ __forceinline__ void load_slab_h(bf16* dst, const bf16* src, size_t ldg,
                                            int k0, int t)
{
    const int row = t >> 1, c0 = (t & 1) * 16;
    const bf16* g = src + (size_t)row * ldg + k0 + c0;
    bf16* s = dst + row * PAD_H + c0;
    cp16(s, g); cp16(s + 8, g + 8);
}

__device__ __forceinline__ void load_slab2_h(bf16* dst, const bf16* src, size_t ldg,
                                             int k0, int t)
{
    const int kk = t >> 3, c0 = (t & 7) * 16;
    const bf16* g = src + (size_t)(k0 + kk) * ldg + c0;
    bf16* s = dst + kk * PAD2_H + c0;
    cp16(s, g); cp16(s + 8, g + 8);
}

__device__ __forceinline__ void ldg_slab_f(float4 (&r)[4], const float* src, int k0, int t)
{
    const int row = t >> 1, c0 = (t & 1) * 16;
    const float* g = src + (size_t)row * CD + k0 + c0;
    r[0] = *(const float4*)(g);
    r[1] = *(const float4*)(g + 4);
    r[2] = *(const float4*)(g + 8);
    r[3] = *(const float4*)(g + 12);
}
__device__ __forceinline__ void sts_slab_cvt(bf16* dst, const float4 (&r)[4], int t)
{
    const int row = t >> 1, c0 = (t & 1) * 16;
    bf16* s = dst + row * PAD_H + c0;
    uint4 o0, o1;
    __nv_bfloat162* p0 = (__nv_bfloat162*)&o0;
    __nv_bfloat162* p1 = (__nv_bfloat162*)&o1;
    p0[0] = __floats2bfloat162_rn(r[0].x, r[0].y);
    p0[1] = __floats2bfloat162_rn(r[0].z, r[0].w);
    p0[2] = __floats2bfloat162_rn(r[1].x, r[1].y);
    p0[3] = __floats2bfloat162_rn(r[1].z, r[1].w);
    p1[0] = __floats2bfloat162_rn(r[2].x, r[2].y);
    p1[1] = __floats2bfloat162_rn(r[2].z, r[2].w);
    p1[2] = __floats2bfloat162_rn(r[3].x, r[3].y);
    p1[3] = __floats2bfloat162_rn(r[3].z, r[3].w);
    *(uint4*)(s)     = o0;
    *(uint4*)(s + 8) = o1;
}

__device__ __forceinline__ void consume_slab(const bf16* Ab, const bf16* Bb,
                                             FACC (&acc)[2][4], int mwl, int nwl)
{
#pragma unroll
    for (int ks = 0; ks < 2; ks++) {
        const int kk = ks * 16;
        FA_R a[2];
        FB_C b[4];
#pragma unroll
        for (int i = 0; i < 2; i++)
            wmma::load_matrix_sync(a[i], Ab + (mwl + 16 * i) * PAD_H + kk, PAD_H);
#pragma unroll
        for (int j = 0; j < 4; j++)
            wmma::load_matrix_sync(b[j], Bb + (nwl + 16 * j) * PAD_H + kk, PAD_H);
#pragma unroll
        for (int i = 0; i < 2; i++)
#pragma unroll
            for (int j = 0; j < 4; j++) wmma::mma_sync(acc[i][j], a[i], b[j], acc[i][j]);
    }
}

__device__ __forceinline__ void mainloop_h(
    const bf16* Xt, size_t ldx, const bf16* Wt, size_t ldw, int NT,
    bf16* As, bf16* Bs, FACC (&acc)[2][4], int tid, int mwl, int nwl)
{
    load_slab_h(As, Xt, ldx, 0, tid);
    load_slab_h(Bs, Wt, ldw, 0, tid);
    cp_commit();
    for (int kt = 0; kt < NT; kt++) {
        const int cur = kt & 1;
        if (kt + 1 < NT) {
            load_slab_h(As + ((kt + 1) & 1) * SLAB_H, Xt, ldx, (kt + 1) * 32, tid);
            load_slab_h(Bs + ((kt + 1) & 1) * SLAB_H, Wt, ldw, (kt + 1) * 32, tid);
            cp_commit();
            cp_wait<1>();
        } else {
            cp_wait<0>();
        }
        __syncthreads();
        consume_slab(As + cur * SLAB_H, Bs + cur * SLAB_H, acc, mwl, nwl);
        __syncthreads();
    }
}

__device__ __forceinline__ void mainloop_f32x(
    const float* Xt, const bf16* Wt, bf16* As, bf16* Bs,
    FACC (&acc)[2][4], int tid, int mwl, int nwl)
{
    float4 rx[4];
    ldg_slab_f(rx, Xt, 0, tid);
    load_slab_h(Bs, Wt, CD, 0, tid);
    cp_commit();
    const int NT = CD / 32;
    for (int kt = 0; kt < NT; kt++) {
        const int cur = kt & 1;
        sts_slab_cvt(As + cur * SLAB_H, rx, tid);
        if (kt + 1 < NT) {
            ldg_slab_f(rx, Xt, (kt + 1) * 32, tid);
            load_slab_h(Bs + ((kt + 1) & 1) * SLAB_H, Wt, CD, (kt + 1) * 32, tid);
            cp_commit();
            cp_wait<1>();
        } else {
            cp_wait<0>();
        }
        __syncthreads();
        consume_slab(As + cur * SLAB_H, Bs + cur * SLAB_H, acc, mwl, nwl);
        __syncthreads();
    }
}

// ---- stage barrier helpers -------------------------------------------------
__device__ __forceinline__ void stage_arrive(int s, int tid)
{
    __syncthreads();
    __threadfence();
    if (tid == 0) atomicAdd(&g_cnt[s], 1);
}
__device__ __forceinline__ void stage_wait(int s, int target, int tid)
{
    if (tid == 0) {
        volatile int* c = &g_cnt[s];
        while (*c < target) __nanosleep(128);
    }
    __syncthreads();
    __threadfence();
}

// ---- epilogue helpers ------------------------------------------------------
__device__ __forceinline__ void epi_bf16(float (*patch)[20], bf16* Y, const float* bias,
                                         int m0, int n0, int wid_unused, int lane)
{
    (void)wid_unused;
    const int pr = lane & 15, pc = (lane >> 4) * 8;
    const int m = m0 + pr;
    const int nb = n0 + pc;
    uint4 o;
    __nv_bfloat162* op = (__nv_bfloat162*)&o;
#pragma unroll
    for (int t = 0; t < 4; t++)
        op[t] = __floats2bfloat162_rn(patch[pr][pc + 2*t]     + (bias ? bias[nb + 2*t] : 0.0f),
                                      patch[pr][pc + 2*t + 1] + (bias ? bias[nb + 2*t + 1] : 0.0f));
    *(uint4*)&Y[(size_t)m * CD + nb] = o;
}

// ---------------------------------------------------------------------------
// THE mega-kernel: 1728 blocks, 6 stages sequenced by device counters.
// ---------------------------------------------------------------------------
__global__ __launch_bounds__(256, 2) void mega_kernel(
    const float* __restrict__ detect, const float* __restrict__ aim,
    const float* __restrict__ g_w,  const float* __restrict__ g_b,
    const float* __restrict__ g2_w, const float* __restrict__ g2_b,
    const float* __restrict__ th_w, const float* __restrict__ th_b,
    const float* __restrict__ ph_w, const float* __restrict__ ph_b,
    const float* __restrict__ W_w,  const float* __restrict__ W_b,
    const float* __restrict__ Q_w,  const float* __restrict__ Q_b,
    float* __restrict__ out_det, float* __restrict__ out_aim)
{
    extern __shared__ bf16 smem[];
    __shared__ float patch[8][16][20];
    const int bid = blockIdx.x;
    const int tid = threadIdx.x, wid = tid >> 5, lane = tid & 31;
    const int wm = wid & 3, wn = wid >> 2;

    // ---------------- Stage 0: weight fp32 -> bf16 (192 blocks) ----------------
    if (bid < B0_LIN4) {
        const int idx = bid;
        const int z = idx >> 5, xb = idx & 31;
        const float* src; bf16* dst;
        if      (z == 0) { src = g_w;  dst = h_wg;  }
        else if (z == 1) { src = g2_w; dst = h_wg2; }
        else if (z == 2) { src = th_w; dst = h_wth; }
        else if (z == 3) { src = ph_w; dst = h_wph; }
        else if (z == 4) { src = W_w;  dst = h_wW;  }
        else             { src = Q_w;  dst = h_wQ;  }
        const int e = (xb * 256 + tid) * 8;
        float4 v0 = *(const float4*)&src[e];
        float4 v1 = *(const float4*)&src[e + 4];
        uint4 o;
        __nv_bfloat162* op = (__nv_bfloat162*)&o;
        op[0] = __floats2bfloat162_rn(v0.x, v0.y);
        op[1] = __floats2bfloat162_rn(v0.z, v0.w);
        op[2] = __floats2bfloat162_rn(v1.x, v1.y);
        op[3] = __floats2bfloat162_rn(v1.z, v1.w);
        *(uint4*)&dst[e] = o;
        stage_arrive(0, tid);
        return;
    }

    // ---------------- Stage 1: front linears (512 blocks) ----------------------
    if (bid < B0_SPART) {
        const int idx = bid - B0_LIN4;
        const int bx = idx & 63, by = (idx >> 6) & 1, z = idx >> 7;
        const float* X; const bf16* W; const float* bias; bf16* Y;
        if      (z == 0) { X = detect; W = h_wg;  bias = g_b;  Y = h_g;     }
        else if (z == 1) { X = aim;    W = h_wg2; bias = g2_b; Y = h_g2;    }
        else if (z == 2) { X = aim;    W = h_wth; bias = th_b; Y = h_theta; }
        else             { X = detect; W = h_wph; bias = ph_b; Y = h_phi;   }

        stage_wait(0, N_CVT, tid);

        FACC acc[2][4];
#pragma unroll
        for (int i = 0; i < 2; i++)
#pragma unroll
            for (int j = 0; j < 4; j++) wmma::fill_fragment(acc[i][j], 0.0f);

        mainloop_f32x(X + (size_t)(bx * 128) * CD, W + (size_t)(by * 128) * CD,
                      smem, smem + 2 * SLAB_H, acc, tid, wm * 32, wn * 64);

        const int m0 = bx * 128 + wm * 32;
        const int n0 = by * 128 + wn * 64;
#pragma unroll
        for (int i = 0; i < 2; i++)
#pragma unroll
            for (int j = 0; j < 4; j++) {
                wmma::store_matrix_sync(&patch[wid][0][0], acc[i][j], 20, wmma::mem_row_major);
                __syncwarp();
                epi_bf16(patch[wid], Y, bias, m0 + 16 * i, n0 + 16 * j, wid, lane);
                __syncwarp();
            }
        stage_arrive(1, tid);
        return;
    }

    // ---------------- Stage 2: split-K partials (256 blocks) -------------------
    if (bid < B0_RED) {
        const int idx = bid - B0_SPART;
        const int split = idx & 31, type = (idx >> 5) & 1, b = idx >> 6;
        stage_wait(1, N_LIN4, tid);

        const bf16* A  = (type ? h_theta : h_phi) + (size_t)b * BSTRIDE;
        const bf16* Bm = (type ? h_g2   : h_g  ) + (size_t)b * BSTRIDE;
        const int kbase = split * (M2 / NSPLIT);

        FACC acc[2][4];
#pragma unroll
        for (int i = 0; i < 2; i++)
#pragma unroll
            for (int j = 0; j < 4; j++) wmma::fill_fragment(acc[i][j], 0.0f);

        mainloop_h(A + kbase, M2, Bm + kbase, M2, (M2 / NSPLIT) / 32,
                   smem, smem + 2 * SLAB_H, acc, tid, wm * 32, wn * 64);

        bf16* out = h_Spart + ((size_t)((type * B_ + b) * NSPLIT + split)) * (ICH * ICH);
#pragma unroll
        for (int i = 0; i < 2; i++)
#pragma unroll
            for (int j = 0; j < 4; j++) {
                wmma::store_matrix_sync(&patch[wid][0][0], acc[i][j], 20, wmma::mem_row_major);
                __syncwarp();
                const int pr = lane & 15, pc = (lane >> 4) * 8;
                const int r = wm * 32 + 16 * i + pr;
                const int c = wn * 64 + 16 * j + pc;
                uint4 o;
                __nv_bfloat162* op = (__nv_bfloat162*)&o;
#pragma unroll
                for (int t = 0; t < 4; t++)
                    op[t] = __floats2bfloat162_rn(patch[wid][pr][pc + 2*t],
                                                  patch[wid][pr][pc + 2*t + 1]);
                *(uint4*)&out[(size_t)r * ICH + c] = o;
                __syncwarp();
            }
        stage_arrive(2, tid);
        return;
    }

    // ---------------- Stage 3: split-K reduce (256 blocks) ---------------------
    if (bid < B0_OUT) {
        const int idx = bid - B0_RED;
        const int xb = idx & 31, mat = idx >> 5;
        stage_wait(2, N_SPART, tid);

        const int e = (xb * 256 + tid) * 2;
        const bf16* base = h_Spart + (size_t)mat * NSPLIT * (ICH * ICH) + e;
        float s0 = 0.0f, s1 = 0.0f;
#pragma unroll
        for (int sp = 0; sp < NSPLIT; sp++) {
            __nv_bfloat162 v = *(const __nv_bfloat162*)(base + (size_t)sp * (ICH * ICH));
            float2 f = __bfloat1622float2(v);
            s0 += f.x; s1 += f.y;
        }
        *(__nv_bfloat162*)&h_S[(size_t)mat * (ICH * ICH) + e] =
            __floats2bfloat162_rn(s0 * (1.0f / 4096.0f), s1 * (1.0f / 4096.0f));
        stage_arrive(3, tid);
        return;
    }

    // ---------------- Stage 4: out_small (256 blocks) --------------------------
    if (bid < B0_LIN2) {
        const int idx = bid - B0_OUT;
        const int bx = idx & 31, type = (idx >> 5) & 1, b = idx >> 6;
        stage_wait(3, N_RED, tid);

        bf16* Ss = smem;
        bf16* Ts = smem + 2 * SLAB2_H;
        const int p0 = bx * 128;
        const bf16* S  = h_S + (size_t)(type * B_ + b) * (ICH * ICH);
        const bf16* Tm = (type ? h_phi : h_theta) + (size_t)b * BSTRIDE;
        bf16* Y = (type ? h_ndT : h_naT) + (size_t)b * BSTRIDE;
        const int iw = wm * 32, pwl = wn * 64;

        FACC acc[2][4];
#pragma unroll
        for (int i = 0; i < 2; i++)
#pragma unroll
            for (int j = 0; j < 4; j++) wmma::fill_fragment(acc[i][j], 0.0f);

        load_slab2_h(Ss, S, ICH, 0, tid);
        load_slab2_h(Ts, Tm + p0, M2, 0, tid);
        cp_commit();
        const int NT = ICH / 32;
#pragma unroll
        for (int kt = 0; kt < NT; kt++) {
            const int cur = kt & 1;
            if (kt + 1 < NT) {
                load_slab2_h(Ss + ((kt + 1) & 1) * SLAB2_H, S, ICH, (kt + 1) * 32, tid);
                load_slab2_h(Ts + ((kt + 1) & 1) * SLAB2_H, Tm + p0, M2, (kt + 1) * 32, tid);
                cp_commit();
                cp_wait<1>();
            } else {
                cp_wait<0>();
            }
            __syncthreads();
            const bf16* Sb = Ss + cur * SLAB2_H;
            const bf16* Tb = Ts + cur * SLAB2_H;
#pragma unroll
            for (int ks = 0; ks < 2; ks++) {
                const int kk = ks * 16;
                FA_C a[2];
                FB_R bf[4];
#pragma unroll
                for (int i = 0; i < 2; i++)
                    wmma::load_matrix_sync(a[i], Sb + kk * PAD2_H + iw + 16 * i, PAD2_H);
#pragma unroll
                for (int j = 0; j < 4; j++)
                    wmma::load_matrix_sync(bf[j], Tb + kk * PAD2_H + pwl + 16 * j, PAD2_H);
#pragma unroll
                for (int i = 0; i < 2; i++)
#pragma unroll
                    for (int j = 0; j < 4; j++) wmma::mma_sync(acc[i][j], a[i], bf[j], acc[i][j]);
            }
            __syncthreads();
        }
        const int pr = lane & 15, pc = (lane >> 4) * 8;
#pragma unroll
        for (int i = 0; i < 2; i++)
#pragma unroll
            for (int j = 0; j < 4; j++) {
                wmma::store_matrix_sync(&patch[wid][0][0], acc[i][j], 20, wmma::mem_row_major);
                __syncwarp();
                const int r = iw + 16 * i + pr;
                const int c = p0 + pwl + 16 * j + pc;
                uint4 o;
                __nv_bfloat162* op = (__nv_bfloat162*)&o;
#pragma unroll
                for (int t = 0; t < 4; t++)
                    op[t] = __floats2bfloat162_rn(patch[wid][pr][pc + 2*t],
                                                  patch[wid][pr][pc + 2*t + 1]);
                *(uint4*)&Y[(size_t)r * M2 + c] = o;
                __syncwarp();
            }
        stage_arrive(4, tid);
        return;
    }

    // ---------------- Stage 5: final linears + residual (256 blocks) -----------
    {
        const int idx = bid - B0_LIN2;
        const int bx = idx & 63, by = (idx >> 6) & 1, z = idx >> 7;
        stage_wait(4, N_OUT, tid);

        const bf16* X = z ? h_naT : h_ndT;
        const bf16* W = z ? h_wW : h_wQ;
        const float* bias = z ? W_b : Q_b;
        const float* res  = z ? aim : detect;
        float* Y = z ? out_aim : out_det;

        FACC acc[2][4];
#pragma unroll
        for (int i = 0; i < 2; i++)
#pragma unroll
            for (int j = 0; j < 4; j++) wmma::fill_fragment(acc[i][j], 0.0f);

        mainloop_h(X + (size_t)(bx * 128) * CD, CD,
                   W + (size_t)(by * 128) * CD, CD, CD / 32,
                   smem, smem + 2 * SLAB_H, acc, tid, wm * 32, wn * 64);

        const int m0 = bx * 128 + wm * 32;
        const int n0 = by * 128 + wn * 64;
        const int pr = lane & 15, pc = (lane >> 4) * 8;
#pragma unroll
        for (int i = 0; i < 2; i++)
#pragma unroll
            for (int j = 0; j < 4; j++) {
                wmma::store_matrix_sync(&patch[wid][0][0], acc[i][j], 20, wmma::mem_row_major);
                __syncwarp();
                const int m = m0 + 16 * i + pr;
                const int nb = n0 + 16 * j + pc;
                const float* rrow = &res[(size_t)m * CD + nb];
                float r[8];
#pragma unroll
                for (int t = 0; t < 8; t++)
                    r[t] = patch[wid][pr][pc + t] + bias[nb + t] + rrow[t];
                float* row = &Y[(size_t)m * CD + nb];
                *(float4*)(row)     = make_float4(r[0], r[1], r[2], r[3]);
                *(float4*)(row + 4) = make_float4(r[4], r[5], r[6], r[7]);
                __syncwarp();
            }

        // arrive + self-reset (last block resets counters for graph replay)
        __syncthreads();
        __threadfence();
        if (tid == 0) {
            int old = atomicAdd(&g_cnt[5], 1);
            if (old == N_LIN2 - 1) {
                g_cnt[0] = 0; g_cnt[1] = 0; g_cnt[2] = 0;
                g_cnt[3] = 0; g_cnt[4] = 0; g_cnt[5] = 0;
                __threadfence();
            }
        }
    }
}

// ---------------------------------------------------------------------------
extern "C" void kernel_launch(void* const* d_in, const int* in_sizes, int n_in,
                              void* d_out, int out_size)
{
    const float* detect = (const float*)d_in[0];
    const float* aim    = (const float*)d_in[1];
    const float* g_w  = (const float*)d_in[2];  const float* g_b  = (const float*)d_in[3];
    const float* g2_w = (const float*)d_in[4];  const float* g2_b = (const float*)d_in[5];
    const float* th_w = (const float*)d_in[6];  const float* th_b = (const float*)d_in[7];
    const float* ph_w = (const float*)d_in[8];  const float* ph_b = (const float*)d_in[9];
    const float* W_w  = (const float*)d_in[10]; const float* W_b  = (const float*)d_in[11];
    const float* Q_w  = (const float*)d_in[12]; const float* Q_b  = (const float*)d_in[13];

    float* out_det = (float*)d_out;
    float* out_aim = out_det + (size_t)B_ * NSEQ * CD;

    const int smemBytes = 4 * SLAB_H * (int)sizeof(bf16);  // 40960 (>= out_small's 34816)
    cudaFuncSetAttribute(mega_kernel, cudaFuncAttributeMaxDynamicSharedMemorySize, smemBytes);

    mega_kernel<<<N_TOTAL, 256, smemBytes>>>(
        detect, aim,
        g_w, g_b, g2_w, g2_b, th_w, th_b, ph_w, ph_b,
        W_w, W_b, Q_w, Q_b,
        out_det, out_aim);
}

// round 14
// speedup vs baseline: 1.3712x; 1.1184x over previous
#include <cuda_runtime.h>
#include <cuda_bf16.h>
#include <mma.h>
#include <cstddef>
#include <cstdint>

using namespace nvcuda;
typedef __nv_bfloat16 bf16;

#define B_    4
#define NSEQ  2048
#define CD    256
#define ICH   128
#define M2    4096                    // 2*NSEQ
#define LIN_ELEMS (B_*NSEQ*CD)        // 2,097,152
#define BSTRIDE   (NSEQ*CD)           // 524,288 per batch
#define NSPLIT    16                  // K=4096 -> 256 per block (R6 config)

// bf16 copies of inputs/weights
__device__ bf16 h_det[LIN_ELEMS];
__device__ bf16 h_aim[LIN_ELEMS];
__device__ bf16 h_wg [CD*CD];
__device__ bf16 h_wg2[CD*CD];
__device__ bf16 h_wth[CD*CD];
__device__ bf16 h_wph[CD*CD];
__device__ bf16 h_wW [CD*CD];
__device__ bf16 h_wQ [CD*CD];
// intermediates (bf16)
__device__ bf16 h_g    [LIN_ELEMS];
__device__ bf16 h_g2   [LIN_ELEMS];
__device__ bf16 h_theta[LIN_ELEMS];
__device__ bf16 h_phi  [LIN_ELEMS];
__device__ bf16 h_S    [2*B_*ICH*ICH];            // scaled by 1/4096
__device__ bf16 h_naT  [LIN_ELEMS];
__device__ bf16 h_ndT  [LIN_ELEMS];
// fp32 split-K partials (R6 precision config)
__device__ float d_Spart[2*B_*NSPLIT*ICH*ICH];

typedef wmma::fragment<wmma::matrix_a, 16, 16, 16, bf16, wmma::row_major> FA_R;
typedef wmma::fragment<wmma::matrix_a, 16, 16, 16, bf16, wmma::col_major> FA_C;
typedef wmma::fragment<wmma::matrix_b, 16, 16, 16, bf16, wmma::row_major> FB_R;
typedef wmma::fragment<wmma::matrix_b, 16, 16, 16, bf16, wmma::col_major> FB_C;
typedef wmma::fragment<wmma::accumulator, 16, 16, 16, float>              FACC;

// ---- cp.async helpers -----------------------------------------------------
__device__ __forceinline__ void cp16(void* s, const void* g) {
    uint32_t sa = (uint32_t)__cvta_generic_to_shared(s);
    asm volatile("cp.async.cg.shared.global [%0], [%1], 16;\n" :: "r"(sa), "l"(g));
}
__device__ __forceinline__ void cp_commit() { asm volatile("cp.async.commit_group;\n"); }
template <int N>
__device__ __forceinline__ void cp_wait() { asm volatile("cp.async.wait_group %0;\n" :: "n"(N)); }

// Row-slab: [128 rows][40 (=32 K + 8 pad)] bf16
#define PAD_H  40
#define SLAB_H (128*PAD_H)
// K-slab (out_small): [32 K][136 (=128 + 8 pad)] bf16
#define PAD2_H  136
#define SLAB2_H (32*PAD2_H)

// 256 threads copy 128x32 bf16 tile (rows, leading dim ldg)
__device__ __forceinline__ void load_slab_h(bf16* dst, const bf16* src, size_t ldg,
                                            int k0, int t)
{
    const int row = t >> 1, c0 = (t & 1) * 16;
    const bf16* g = src + (size_t)row * ldg + k0 + c0;
    bf16* s = dst + row * PAD_H + c0;
    cp16(s, g); cp16(s + 8, g + 8);
}

// 256 threads copy 32x128 bf16 tile (K-major rows, leading dim ldg)
__device__ __forceinline__ void load_slab2_h(bf16* dst, const bf16* src, size_t ldg,
                                             int k0, int t)
{
    const int kk = t >> 3, c0 = (t & 7) * 16;
    const bf16* g = src + (size_t)(k0 + kk) * ldg + c0;
    bf16* s = dst + kk * PAD2_H + c0;
    cp16(s, g); cp16(s + 8, g + 8);
}

// Mainloop: C[128x128] += A(rowslab) x B(rowslab)^T, K = NT*32, bf16 MMA. (R6)
__device__ __forceinline__ void mainloop_h(
    const bf16* Xt, size_t ldx, const bf16* Wt, size_t ldw, int NT,
    bf16* As, bf16* Bs, FACC (&acc)[2][4], int tid, int mwl, int nwl)
{
    load_slab_h(As, Xt, ldx, 0, tid);
    load_slab_h(Bs, Wt, ldw, 0, tid);
    cp_commit();
    for (int kt = 0; kt < NT; kt++) {
        const int cur = kt & 1;
        if (kt + 1 < NT) {
            load_slab_h(As + ((kt + 1) & 1) * SLAB_H, Xt, ldx, (kt + 1) * 32, tid);
            load_slab_h(Bs + ((kt + 1) & 1) * SLAB_H, Wt, ldw, (kt + 1) * 32, tid);
            cp_commit();
            cp_wait<1>();
        } else {
            cp_wait<0>();
        }
        __syncthreads();
        const bf16* Ab = As + cur * SLAB_H;
        const bf16* Bb = Bs + cur * SLAB_H;
#pragma unroll
        for (int ks = 0; ks < 2; ks++) {
            const int kk = ks * 16;
            FA_R a[2];
            FB_C b[4];
#pragma unroll
            for (int i = 0; i < 2; i++)
                wmma::load_matrix_sync(a[i], Ab + (mwl + 16 * i) * PAD_H + kk, PAD_H);
#pragma unroll
            for (int j = 0; j < 4; j++)
                wmma::load_matrix_sync(b[j], Bb + (nwl + 16 * j) * PAD_H + kk, PAD_H);
#pragma unroll
            for (int i = 0; i < 2; i++)
#pragma unroll
                for (int j = 0; j < 4; j++) wmma::mma_sync(acc[i][j], a[i], b[j], acc[i][j]);
        }
        __syncthreads();
    }
}

// ---------------------------------------------------------------------------
// Stage 0: fp32 -> bf16 conversion of inputs + weights. grid (1024, 8).
// ---------------------------------------------------------------------------
__global__ __launch_bounds__(256) void cvt_kernel(
    const float* __restrict__ det, const float* __restrict__ aim,
    const float* __restrict__ w0, const float* __restrict__ w1,
    const float* __restrict__ w2, const float* __restrict__ w3,
    const float* __restrict__ w4, const float* __restrict__ w5)
{
    const int z = blockIdx.y;
    const float* src; bf16* dst; int n;
    if      (z == 0) { src = det; dst = h_det; n = LIN_ELEMS; }
    else if (z == 1) { src = aim; dst = h_aim; n = LIN_ELEMS; }
    else if (z == 2) { src = w0; dst = h_wg;  n = CD*CD; }
    else if (z == 3) { src = w1; dst = h_wg2; n = CD*CD; }
    else if (z == 4) { src = w2; dst = h_wth; n = CD*CD; }
    else if (z == 5) { src = w3; dst = h_wph; n = CD*CD; }
    else if (z == 6) { src = w4; dst = h_wW;  n = CD*CD; }
    else             { src = w5; dst = h_wQ;  n = CD*CD; }
    const int idx = (blockIdx.x * 256 + threadIdx.x) * 8;
    if (idx >= n) return;
    float4 v0 = *(const float4*)&src[idx];
    float4 v1 = *(const float4*)&src[idx + 4];
    uint4 o;
    __nv_bfloat162* op = (__nv_bfloat162*)&o;
    op[0] = __floats2bfloat162_rn(v0.x, v0.y);
    op[1] = __floats2bfloat162_rn(v0.z, v0.w);
    op[2] = __floats2bfloat162_rn(v1.x, v1.y);
    op[3] = __floats2bfloat162_rn(v1.z, v1.w);
    *(uint4*)&dst[idx] = o;
}

// ---------------------------------------------------------------------------
// Stage 1 (per batch): front linears, bf16 in/out. grid (16, 2, 4)
// ---------------------------------------------------------------------------
__global__ __launch_bounds__(256, 2) void lin4_tc(
    const float* __restrict__ b0, const float* __restrict__ b1,
    const float* __restrict__ b2, const float* __restrict__ b3,
    int batch)
{
    extern __shared__ bf16 smem[];
    __shared__ float patch[8][16][20];
    const int z = blockIdx.z;
    const bf16* X; const bf16* W; const float* bias; bf16* Y;
    if      (z == 0) { X = h_det; W = h_wg;  bias = b0; Y = h_g;     }
    else if (z == 1) { X = h_aim; W = h_wg2; bias = b1; Y = h_g2;    }
    else if (z == 2) { X = h_aim; W = h_wth; bias = b2; Y = h_theta; }
    else             { X = h_det; W = h_wph; bias = b3; Y = h_phi;   }

    const int tid = threadIdx.x, wid = tid >> 5, lane = tid & 31;
    const int wm = wid & 3, wn = wid >> 2;
    const int m0b = batch * NSEQ + blockIdx.x * 128;
    const int n0 = blockIdx.y * 128;

    FACC acc[2][4];
#pragma unroll
    for (int i = 0; i < 2; i++)
#pragma unroll
        for (int j = 0; j < 4; j++) wmma::fill_fragment(acc[i][j], 0.0f);

    mainloop_h(X + (size_t)m0b * CD, CD, W + (size_t)n0 * CD, CD, CD / 32,
               smem, smem + 2 * SLAB_H, acc, tid, wm * 32, wn * 64);

    const int m0 = m0b + wm * 32;
    const int n0w = n0 + wn * 64;
    const int pr = lane & 15, pc = (lane >> 4) * 8;
#pragma unroll
    for (int i = 0; i < 2; i++)
#pragma unroll
        for (int j = 0; j < 4; j++) {
            wmma::store_matrix_sync(&patch[wid][0][0], acc[i][j], 20, wmma::mem_row_major);
            __syncwarp();
            const int m = m0 + 16 * i + pr;
            const int nb = n0w + 16 * j + pc;
            uint4 o;
            __nv_bfloat162* op = (__nv_bfloat162*)&o;
#pragma unroll
            for (int t = 0; t < 4; t++)
                op[t] = __floats2bfloat162_rn(patch[wid][pr][pc + 2*t]     + bias[nb + 2*t],
                                              patch[wid][pr][pc + 2*t + 1] + bias[nb + 2*t + 1]);
            *(uint4*)&Y[(size_t)m * CD + nb] = o;
            __syncwarp();
        }
}

// ---------------------------------------------------------------------------
// Stage 2 (per batch): split-K partials (fp32 out). grid (NSPLIT, 2)
// ---------------------------------------------------------------------------
__global__ __launch_bounds__(256, 2) void s_partial_tc(int b)
{
    extern __shared__ bf16 smem[];
    const int split = blockIdx.x, type = blockIdx.y;
    const bf16* A  = (type ? h_theta : h_phi) + (size_t)b * BSTRIDE;
    const bf16* Bm = (type ? h_g2   : h_g  ) + (size_t)b * BSTRIDE;
    const int kbase = split * (M2 / NSPLIT);
    const int tid = threadIdx.x, wid = tid >> 5;
    const int wm = wid & 3, wn = wid >> 2;

    FACC acc[2][4];
#pragma unroll
    for (int i = 0; i < 2; i++)
#pragma unroll
        for (int j = 0; j < 4; j++) wmma::fill_fragment(acc[i][j], 0.0f);

    mainloop_h(A + kbase, M2, Bm + kbase, M2, (M2 / NSPLIT) / 32,
               smem, smem + 2 * SLAB_H, acc, tid, wm * 32, wn * 64);

    float* out = d_Spart + ((size_t)((type * B_ + b) * NSPLIT + split)) * (ICH * ICH);
#pragma unroll
    for (int i = 0; i < 2; i++)
#pragma unroll
        for (int j = 0; j < 4; j++)
            wmma::store_matrix_sync(out + (size_t)(wm * 32 + 16 * i) * ICH + wn * 64 + 16 * j,
                                    acc[i][j], ICH, wmma::mem_row_major);
}

// ---------------------------------------------------------------------------
// Stage 3 (per batch): reduce fp32 partials, scale 1/4096, bf16 out. grid (64, 2)
// ---------------------------------------------------------------------------
__global__ __launch_bounds__(256) void s_reduce_kernel(int b)
{
    const int e = blockIdx.x * 256 + threadIdx.x;
    const int mat = blockIdx.y * B_ + b;
    const float* base = d_Spart + (size_t)mat * NSPLIT * (ICH * ICH) + e;
    float s = 0.0f;
#pragma unroll
    for (int sp = 0; sp < NSPLIT; sp++) s += base[(size_t)sp * (ICH * ICH)];
    h_S[(size_t)mat * (ICH * ICH) + e] = __float2bfloat16(s * (1.0f / 4096.0f));
}

// ---------------------------------------------------------------------------
// Stage 4 (per batch): C[i,p] = sum_k S[k,i] * Tm[k,p]. grid (32, 2)
// ---------------------------------------------------------------------------
__global__ __launch_bounds__(256, 2) void out_small_tc(int b)
{
    extern __shared__ bf16 smem[];
    bf16* Ss = smem;
    bf16* Ts = smem + 2 * SLAB2_H;
    __shared__ float patch[8][16][20];
    const int p0 = blockIdx.x * 128, type = blockIdx.y;
    const bf16* S  = h_S + (size_t)(type * B_ + b) * (ICH * ICH);
    const bf16* Tm = (type ? h_phi : h_theta) + (size_t)b * BSTRIDE;
    bf16* Y = (type ? h_ndT : h_naT) + (size_t)b * BSTRIDE;
    const int tid = threadIdx.x, wid = tid >> 5, lane = tid & 31;
    const int wm = wid & 3, wn = wid >> 2;
    const int iw = wm * 32, pwl = wn * 64;

    FACC acc[2][4];
#pragma unroll
    for (int i = 0; i < 2; i++)
#pragma unroll
        for (int j = 0; j < 4; j++) wmma::fill_fragment(acc[i][j], 0.0f);

    load_slab2_h(Ss, S, ICH, 0, tid);
    load_slab2_h(Ts, Tm + p0, M2, 0, tid);
    cp_commit();
    const int NT = ICH / 32;            // 4
    for (int kt = 0; kt < NT; kt++) {
        const int cur = kt & 1;
        if (kt + 1 < NT) {
            load_slab2_h(Ss + ((kt + 1) & 1) * SLAB2_H, S, ICH, (kt + 1) * 32, tid);
            load_slab2_h(Ts + ((kt + 1) & 1) * SLAB2_H, Tm + p0, M2, (kt + 1) * 32, tid);
            cp_commit();
            cp_wait<1>();
        } else {
            cp_wait<0>();
        }
        __syncthreads();
        const bf16* Sb = Ss + cur * SLAB2_H;
        const bf16* Tb = Ts + cur * SLAB2_H;
#pragma unroll
        for (int ks = 0; ks < 2; ks++) {
            const int kk = ks * 16;
            FA_C a[2];
            FB_R bf[4];
#pragma unroll
            for (int i = 0; i < 2; i++)
                wmma::load_matrix_sync(a[i], Sb + kk * PAD2_H + iw + 16 * i, PAD2_H);
#pragma unroll
            for (int j = 0; j < 4; j++)
                wmma::load_matrix_sync(bf[j], Tb + kk * PAD2_H + pwl + 16 * j, PAD2_H);
#pragma unroll
            for (int i = 0; i < 2; i++)
#pragma unroll
                for (int j = 0; j < 4; j++) wmma::mma_sync(acc[i][j], a[i], bf[j], acc[i][j]);
        }
        __syncthreads();
    }
    const int pr = lane & 15, pc = (lane >> 4) * 8;
#pragma unroll
    for (int i = 0; i < 2; i++)
#pragma unroll
        for (int j = 0; j < 4; j++) {
            wmma::store_matrix_sync(&patch[wid][0][0], acc[i][j], 20, wmma::mem_row_major);
            __syncwarp();
            const int r = iw + 16 * i + pr;
            const int c = p0 + pwl + 16 * j + pc;
            uint4 o;
            __nv_bfloat162* op = (__nv_bfloat162*)&o;
#pragma unroll
            for (int t = 0; t < 4; t++)
                op[t] = __floats2bfloat162_rn(patch[wid][pr][pc + 2*t], patch[wid][pr][pc + 2*t + 1]);
            *(uint4*)&Y[(size_t)r * M2 + c] = o;
            __syncwarp();
        }
}

// ---------------------------------------------------------------------------
// Stage 5 (per batch): final linears + residual (fp32 out). grid (16, 2, 2)
// ---------------------------------------------------------------------------
__global__ __launch_bounds__(256, 2) void lin2_tc(
    const float* __restrict__ Qb, const float* __restrict__ det,
    const float* __restrict__ Wb, const float* __restrict__ aim,
    float* __restrict__ out_det, float* __restrict__ out_aim,
    int batch)
{
    extern __shared__ bf16 smem[];
    __shared__ float patch[8][16][20];
    const int z = blockIdx.z;
    const bf16* X = z ? h_naT : h_ndT;
    const bf16* W = z ? h_wW : h_wQ;
    const float* bias = z ? Wb : Qb;
    const float* res  = z ? aim : det;
    float* Y = z ? out_aim : out_det;

    const int tid = threadIdx.x, wid = tid >> 5, lane = tid & 31;
    const int wm = wid & 3, wn = wid >> 2;
    const int m0b = batch * NSEQ + blockIdx.x * 128;
    const int n0 = blockIdx.y * 128;

    FACC acc[2][4];
#pragma unroll
    for (int i = 0; i < 2; i++)
#pragma unroll
        for (int j = 0; j < 4; j++) wmma::fill_fragment(acc[i][j], 0.0f);

    mainloop_h(X + (size_t)m0b * CD, CD, W + (size_t)n0 * CD, CD, CD / 32,
               smem, smem + 2 * SLAB_H, acc, tid, wm * 32, wn * 64);

    const int m0 = m0b + wm * 32;
    const int n0w = n0 + wn * 64;
    const int pr = lane & 15, pc = (lane >> 4) * 8;
#pragma unroll
    for (int i = 0; i < 2; i++)
#pragma unroll
        for (int j = 0; j < 4; j++) {
            wmma::store_matrix_sync(&patch[wid][0][0], acc[i][j], 20, wmma::mem_row_major);
            __syncwarp();
            const int m = m0 + 16 * i + pr;
            const int nb = n0w + 16 * j + pc;
            const float* rrow = &res[(size_t)m * CD + nb];
            float r[8];
#pragma unroll
            for (int t = 0; t < 8; t++)
                r[t] = patch[wid][pr][pc + t] + bias[nb + t] + rrow[t];
            float* row = &Y[(size_t)m * CD + nb];
            *(float4*)(row)     = make_float4(r[0], r[1], r[2], r[3]);
            *(float4*)(row + 4) = make_float4(r[4], r[5], r[6], r[7]);
            __syncwarp();
        }
}

// ---------------------------------------------------------------------------
extern "C" void kernel_launch(void* const* d_in, const int* in_sizes, int n_in,
                              void* d_out, int out_size)
{
    const float* detect = (const float*)d_in[0];
    const float* aim    = (const float*)d_in[1];
    const float* g_w  = (const float*)d_in[2];  const float* g_b  = (const float*)d_in[3];
    const float* g2_w = (const float*)d_in[4];  const float* g2_b = (const float*)d_in[5];
    const float* th_w = (const float*)d_in[6];  const float* th_b = (const float*)d_in[7];
    const float* ph_w = (const float*)d_in[8];  const float* ph_b = (const float*)d_in[9];
    const float* W_w  = (const float*)d_in[10]; const float* W_b  = (const float*)d_in[11];
    const float* Q_w  = (const float*)d_in[12]; const float* Q_b  = (const float*)d_in[13];

    float* out_det = (float*)d_out;
    float* out_aim = out_det + (size_t)B_ * NSEQ * CD;

    const int smemLin = 4 * SLAB_H * (int)sizeof(bf16);    // 40960
    const int smemOut = 4 * SLAB2_H * (int)sizeof(bf16);   // 34816
    cudaFuncSetAttribute(lin4_tc,      cudaFuncAttributeMaxDynamicSharedMemorySize, smemLin);
    cudaFuncSetAttribute(s_partial_tc, cudaFuncAttributeMaxDynamicSharedMemorySize, smemLin);
    cudaFuncSetAttribute(out_small_tc, cudaFuncAttributeMaxDynamicSharedMemorySize, smemOut);
    cudaFuncSetAttribute(lin2_tc,      cudaFuncAttributeMaxDynamicSharedMemorySize, smemLin);

    // forked-capture per-batch chains: 4 streams + events (host objects only)
    cudaStream_t st[B_];
    cudaEvent_t evRoot, evDone[B_];
    for (int b = 0; b < B_; b++)
        cudaStreamCreateWithFlags(&st[b], cudaStreamNonBlocking);
    cudaEventCreateWithFlags(&evRoot, cudaEventDisableTiming);
    for (int b = 0; b < B_; b++)
        cudaEventCreateWithFlags(&evDone[b], cudaEventDisableTiming);

    // Stage 0 on the captured origin stream
    cvt_kernel<<<dim3(LIN_ELEMS / (256 * 8), 8), 256>>>(
        detect, aim, g_w, g2_w, th_w, ph_w, W_w, Q_w);
    cudaEventRecord(evRoot, 0);

    for (int b = 0; b < B_; b++) {
        cudaStreamWaitEvent(st[b], evRoot, 0);
        lin4_tc<<<dim3(16, 2, 4), 256, smemLin, st[b]>>>(g_b, g2_b, th_b, ph_b, b);
        s_partial_tc<<<dim3(NSPLIT, 2), 256, smemLin, st[b]>>>(b);
        s_reduce_kernel<<<dim3(64, 2), 256, 0, st[b]>>>(b);
        out_small_tc<<<dim3(M2 / 128, 2), 256, smemOut, st[b]>>>(b);
        lin2_tc<<<dim3(16, 2, 2), 256, smemLin, st[b]>>>(
            Q_b, detect, W_b, aim, out_det, out_aim, b);
        cudaEventRecord(evDone[b], st[b]);
    }
    for (int b = 0; b < B_; b++)
        cudaStreamWaitEvent(0, evDone[b], 0);

    for (int b = 0; b < B_; b++) cudaStreamDestroy(st[b]);
    cudaEventDestroy(evRoot);
    for (int b = 0; b < B_; b++) cudaEventDestroy(evDone[b]);
}

// round 16
// speedup vs baseline: 1.4208x; 1.0361x over previous
#include <cuda_runtime.h>
#include <cuda_bf16.h>
#include <mma.h>
#include <cstddef>
#include <cstdint>

using namespace nvcuda;
typedef __nv_bfloat16 bf16;

#define B_    4
#define NSEQ  2048
#define CD    256
#define ICH   128
#define M2    4096                    // 2*NSEQ
#define LIN_ELEMS (B_*NSEQ*CD)        // 2,097,152
#define BSTRIDE   (NSEQ*CD)           // 524,288 per batch
#define NSPLIT    16                  // K=4096 -> 256 per block

// bf16 copies of inputs/weights
__device__ bf16 h_det[LIN_ELEMS];
__device__ bf16 h_aim[LIN_ELEMS];
__device__ bf16 h_wg [CD*CD];
__device__ bf16 h_wg2[CD*CD];
__device__ bf16 h_wth[CD*CD];
__device__ bf16 h_wph[CD*CD];
__device__ bf16 h_wW [CD*CD];
__device__ bf16 h_wQ [CD*CD];
// intermediates (bf16)
__device__ bf16 h_g    [LIN_ELEMS];
__device__ bf16 h_g2   [LIN_ELEMS];
__device__ bf16 h_theta[LIN_ELEMS];
__device__ bf16 h_phi  [LIN_ELEMS];
__device__ bf16 h_S    [2*B_*ICH*ICH];            // scaled by 1/4096
__device__ bf16 h_naT  [LIN_ELEMS];
__device__ bf16 h_ndT  [LIN_ELEMS];
// fp32 split-K partials
__device__ float d_Spart[2*B_*NSPLIT*ICH*ICH];

typedef wmma::fragment<wmma::matrix_a, 16, 16, 16, bf16, wmma::row_major> FA_R;
typedef wmma::fragment<wmma::matrix_a, 16, 16, 16, bf16, wmma::col_major> FA_C;
typedef wmma::fragment<wmma::matrix_b, 16, 16, 16, bf16, wmma::row_major> FB_R;
typedef wmma::fragment<wmma::matrix_b, 16, 16, 16, bf16, wmma::col_major> FB_C;
typedef wmma::fragment<wmma::accumulator, 16, 16, 16, float>              FACC;

// ---- cp.async helpers -----------------------------------------------------
__device__ __forceinline__ void cp16(void* s, const void* g) {
    uint32_t sa = (uint32_t)__cvta_generic_to_shared(s);
    asm volatile("cp.async.cg.shared.global [%0], [%1], 16;\n" :: "r"(sa), "l"(g));
}
__device__ __forceinline__ void cp_commit() { asm volatile("cp.async.commit_group;\n"); }
template <int N>
__device__ __forceinline__ void cp_wait() { asm volatile("cp.async.wait_group %0;\n" :: "n"(N)); }

// Row-slab: [128 rows][40 (=32 K + 8 pad)] bf16
#define PAD_H  40
#define SLAB_H (128*PAD_H)
// K-slab (out_small): [32 K][136 (=128 + 8 pad)] bf16
#define PAD2_H  136
#define SLAB2_H (32*PAD2_H)

// 256 threads copy 128x32 bf16 tile (rows, leading dim ldg)
__device__ __forceinline__ void load_slab_h(bf16* dst, const bf16* src, size_t ldg,
                                            int k0, int t)
{
    const int row = t >> 1, c0 = (t & 1) * 16;
    const bf16* g = src + (size_t)row * ldg + k0 + c0;
    bf16* s = dst + row * PAD_H + c0;
    cp16(s, g); cp16(s + 8, g + 8);
}

// 256 threads copy 32x128 bf16 tile (K-major rows, leading dim ldg)
__device__ __forceinline__ void load_slab2_h(bf16* dst, const bf16* src, size_t ldg,
                                             int k0, int t)
{
    const int kk = t >> 3, c0 = (t & 7) * 16;
    const bf16* g = src + (size_t)(k0 + kk) * ldg + c0;
    bf16* s = dst + kk * PAD2_H + c0;
    cp16(s, g); cp16(s + 8, g + 8);
}

// Consume one 32-K row-slab pair
__device__ __forceinline__ void consume_slab(const bf16* Ab, const bf16* Bb,
                                             FACC (&acc)[2][4], int mwl, int nwl)
{
#pragma unroll
    for (int ks = 0; ks < 2; ks++) {
        const int kk = ks * 16;
        FA_R a[2];
        FB_C b[4];
#pragma unroll
        for (int i = 0; i < 2; i++)
            wmma::load_matrix_sync(a[i], Ab + (mwl + 16 * i) * PAD_H + kk, PAD_H);
#pragma unroll
        for (int j = 0; j < 4; j++)
            wmma::load_matrix_sync(b[j], Bb + (nwl + 16 * j) * PAD_H + kk, PAD_H);
#pragma unroll
        for (int i = 0; i < 2; i++)
#pragma unroll
            for (int j = 0; j < 4; j++) wmma::mma_sync(acc[i][j], a[i], b[j], acc[i][j]);
    }
}

// Triple-buffer single-sync mainloop.  Loads issued 2 iters ahead; the buffer
// written at iter kt ((kt+2)%3 == (kt-1)%3) was fully consumed before this
// iteration's barrier, so ONE __syncthreads per slab suffices.
template <int NT>
__device__ __forceinline__ void mainloop_h3s(
    const bf16* Xt, size_t ldx, const bf16* Wt, size_t ldw,
    bf16* As, bf16* Bs, FACC (&acc)[2][4], int tid, int mwl, int nwl)
{
    load_slab_h(As, Xt, ldx, 0, tid);
    load_slab_h(Bs, Wt, ldw, 0, tid);
    cp_commit();
    if (NT > 1) {
        load_slab_h(As + SLAB_H, Xt, ldx, 32, tid);
        load_slab_h(Bs + SLAB_H, Wt, ldw, 32, tid);
        cp_commit();
    }
#pragma unroll
    for (int kt = 0; kt < NT; kt++) {
        const int cur = kt % 3;
        if (kt + 1 < NT) cp_wait<1>(); else cp_wait<0>();
        __syncthreads();
        if (kt + 2 < NT) {
            const int nxt = (kt + 2) % 3;
            load_slab_h(As + nxt * SLAB_H, Xt, ldx, (kt + 2) * 32, tid);
            load_slab_h(Bs + nxt * SLAB_H, Wt, ldw, (kt + 2) * 32, tid);
            cp_commit();
        }
        consume_slab(As + cur * SLAB_H, Bs + cur * SLAB_H, acc, mwl, nwl);
    }
    __syncthreads();
}

// ---------------------------------------------------------------------------
// Stage 0: fp32 -> bf16 conversion of inputs + weights. grid (1024, 8).
// ---------------------------------------------------------------------------
__global__ __launch_bounds__(256) void cvt_kernel(
    const float* __restrict__ det, const float* __restrict__ aim,
    const float* __restrict__ w0, const float* __restrict__ w1,
    const float* __restrict__ w2, const float* __restrict__ w3,
    const float* __restrict__ w4, const float* __restrict__ w5)
{
    const int z = blockIdx.y;
    const float* src; bf16* dst; int n;
    if      (z == 0) { src = det; dst = h_det; n = LIN_ELEMS; }
    else if (z == 1) { src = aim; dst = h_aim; n = LIN_ELEMS; }
    else if (z == 2) { src = w0; dst = h_wg;  n = CD*CD; }
    else if (z == 3) { src = w1; dst = h_wg2; n = CD*CD; }
    else if (z == 4) { src = w2; dst = h_wth; n = CD*CD; }
    else if (z == 5) { src = w3; dst = h_wph; n = CD*CD; }
    else if (z == 6) { src = w4; dst = h_wW;  n = CD*CD; }
    else             { src = w5; dst = h_wQ;  n = CD*CD; }
    const int idx = (blockIdx.x * 256 + threadIdx.x) * 8;
    if (idx >= n) return;
    float4 v0 = *(const float4*)&src[idx];
    float4 v1 = *(const float4*)&src[idx + 4];
    uint4 o;
    __nv_bfloat162* op = (__nv_bfloat162*)&o;
    op[0] = __floats2bfloat162_rn(v0.x, v0.y);
    op[1] = __floats2bfloat162_rn(v0.z, v0.w);
    op[2] = __floats2bfloat162_rn(v1.x, v1.y);
    op[3] = __floats2bfloat162_rn(v1.z, v1.w);
    *(uint4*)&dst[idx] = o;
}

// ---------------------------------------------------------------------------
// Stage 1 (per batch): front linears, bf16 in/out. grid (16, 2, 4)
// ---------------------------------------------------------------------------
__global__ __launch_bounds__(256, 2) void lin4_tc(
    const float* __restrict__ b0, const float* __restrict__ b1,
    const float* __restrict__ b2, const float* __restrict__ b3,
    int batch)
{
    extern __shared__ bf16 smem[];
    __shared__ float patch[8][16][20];
    const int z = blockIdx.z;
    const bf16* X; const bf16* W; const float* bias; bf16* Y;
    if      (z == 0) { X = h_det; W = h_wg;  bias = b0; Y = h_g;     }
    else if (z == 1) { X = h_aim; W = h_wg2; bias = b1; Y = h_g2;    }
    else if (z == 2) { X = h_aim; W = h_wth; bias = b2; Y = h_theta; }
    else             { X = h_det; W = h_wph; bias = b3; Y = h_phi;   }

    const int tid = threadIdx.x, wid = tid >> 5, lane = tid & 31;
    const int wm = wid & 3, wn = wid >> 2;
    const int m0b = batch * NSEQ + blockIdx.x * 128;
    const int n0 = blockIdx.y * 128;

    FACC acc[2][4];
#pragma unroll
    for (int i = 0; i < 2; i++)
#pragma unroll
        for (int j = 0; j < 4; j++) wmma::fill_fragment(acc[i][j], 0.0f);

    mainloop_h3s<CD / 32>(X + (size_t)m0b * CD, CD, W + (size_t)n0 * CD, CD,
                          smem, smem + 3 * SLAB_H, acc, tid, wm * 32, wn * 64);

    const int m0 = m0b + wm * 32;
    const int n0w = n0 + wn * 64;
    const int pr = lane & 15, pc = (lane >> 4) * 8;
#pragma unroll
    for (int i = 0; i < 2; i++)
#pragma unroll
        for (int j = 0; j < 4; j++) {
            wmma::store_matrix_sync(&patch[wid][0][0], acc[i][j], 20, wmma::mem_row_major);
            __syncwarp();
            const int m = m0 + 16 * i + pr;
            const int nb = n0w + 16 * j + pc;
            uint4 o;
            __nv_bfloat162* op = (__nv_bfloat162*)&o;
#pragma unroll
            for (int t = 0; t < 4; t++)
                op[t] = __floats2bfloat162_rn(patch[wid][pr][pc + 2*t]     + bias[nb + 2*t],
                                              patch[wid][pr][pc + 2*t + 1] + bias[nb + 2*t + 1]);
            *(uint4*)&Y[(size_t)m * CD + nb] = o;
            __syncwarp();
        }
}

// ---------------------------------------------------------------------------
// Stage 2 (per batch): split-K partials (fp32 out). grid (NSPLIT, 2)
// ---------------------------------------------------------------------------
__global__ __launch_bounds__(256, 2) void s_partial_tc(int b)
{
    extern __shared__ bf16 smem[];
    const int split = blockIdx.x, type = blockIdx.y;
    const bf16* A  = (type ? h_theta : h_phi) + (size_t)b * BSTRIDE;
    const bf16* Bm = (type ? h_g2   : h_g  ) + (size_t)b * BSTRIDE;
    const int kbase = split * (M2 / NSPLIT);
    const int tid = threadIdx.x, wid = tid >> 5;
    const int wm = wid & 3, wn = wid >> 2;

    FACC acc[2][4];
#pragma unroll
    for (int i = 0; i < 2; i++)
#pragma unroll
        for (int j = 0; j < 4; j++) wmma::fill_fragment(acc[i][j], 0.0f);

    mainloop_h3s<(M2 / NSPLIT) / 32>(A + kbase, M2, Bm + kbase, M2,
                                     smem, smem + 3 * SLAB_H, acc, tid, wm * 32, wn * 64);

    float* out = d_Spart + ((size_t)((type * B_ + b) * NSPLIT + split)) * (ICH * ICH);
#pragma unroll
    for (int i = 0; i < 2; i++)
#pragma unroll
        for (int j = 0; j < 4; j++)
            wmma::store_matrix_sync(out + (size_t)(wm * 32 + 16 * i) * ICH + wn * 64 + 16 * j,
                                    acc[i][j], ICH, wmma::mem_row_major);
}

// ---------------------------------------------------------------------------
// Stage 3 (per batch): reduce fp32 partials, scale 1/4096, bf16 out. grid (64, 2)
// ---------------------------------------------------------------------------
__global__ __launch_bounds__(256) void s_reduce_kernel(int b)
{
    const int e = blockIdx.x * 256 + threadIdx.x;
    const int mat = blockIdx.y * B_ + b;
    const float* base = d_Spart + (size_t)mat * NSPLIT * (ICH * ICH) + e;
    float s = 0.0f;
#pragma unroll
    for (int sp = 0; sp < NSPLIT; sp++) s += base[(size_t)sp * (ICH * ICH)];
    h_S[(size_t)mat * (ICH * ICH) + e] = __float2bfloat16(s * (1.0f / 4096.0f));
}

// ---------------------------------------------------------------------------
// Stage 4 (per batch): C[i,p] = sum_k S[k,i] * Tm[k,p]. grid (32, 2)
// Triple-buffer single-sync over 4 K-slabs.
// ---------------------------------------------------------------------------
__global__ __launch_bounds__(256, 2) void out_small_tc(int b)
{
    extern __shared__ bf16 smem[];
    bf16* Ss = smem;
    bf16* Ts = smem + 3 * SLAB2_H;
    __shared__ float patch[8][16][20];
    const int p0 = blockIdx.x * 128, type = blockIdx.y;
    const bf16* S  = h_S + (size_t)(type * B_ + b) * (ICH * ICH);
    const bf16* Tm = (type ? h_phi : h_theta) + (size_t)b * BSTRIDE;
    bf16* Y = (type ? h_ndT : h_naT) + (size_t)b * BSTRIDE;
    const int tid = threadIdx.x, wid = tid >> 5, lane = tid & 31;
    const int wm = wid & 3, wn = wid >> 2;
    const int iw = wm * 32, pwl = wn * 64;

    FACC acc[2][4];
#pragma unroll
    for (int i = 0; i < 2; i++)
#pragma unroll
        for (int j = 0; j < 4; j++) wmma::fill_fragment(acc[i][j], 0.0f);

    load_slab2_h(Ss, S, ICH, 0, tid);
    load_slab2_h(Ts, Tm + p0, M2, 0, tid);
    cp_commit();
    load_slab2_h(Ss + SLAB2_H, S, ICH, 32, tid);
    load_slab2_h(Ts + SLAB2_H, Tm + p0, M2, 32, tid);
    cp_commit();
    const int NT = ICH / 32;            // 4
#pragma unroll
    for (int kt = 0; kt < NT; kt++) {
        const int cur = kt % 3;
        if (kt + 1 < NT) cp_wait<1>(); else cp_wait<0>();
        __syncthreads();
        if (kt + 2 < NT) {
            const int nxt = (kt + 2) % 3;
            load_slab2_h(Ss + nxt * SLAB2_H, S, ICH, (kt + 2) * 32, tid);
            load_slab2_h(Ts + nxt * SLAB2_H, Tm + p0, M2, (kt + 2) * 32, tid);
            cp_commit();
        }
        const bf16* Sb = Ss + cur * SLAB2_H;
        const bf16* Tb = Ts + cur * SLAB2_H;
#pragma unroll
        for (int ks = 0; ks < 2; ks++) {
            const int kk = ks * 16;
            FA_C a[2];
            FB_R bf[4];
#pragma unroll
            for (int i = 0; i < 2; i++)
                wmma::load_matrix_sync(a[i], Sb + kk * PAD2_H + iw + 16 * i, PAD2_H);
#pragma unroll
            for (int j = 0; j < 4; j++)
                wmma::load_matrix_sync(bf[j], Tb + kk * PAD2_H + pwl + 16 * j, PAD2_H);
#pragma unroll
            for (int i = 0; i < 2; i++)
#pragma unroll
                for (int j = 0; j < 4; j++) wmma::mma_sync(acc[i][j], a[i], bf[j], acc[i][j]);
        }
    }
    __syncthreads();
    const int pr = lane & 15, pc = (lane >> 4) * 8;
#pragma unroll
    for (int i = 0; i < 2; i++)
#pragma unroll
        for (int j = 0; j < 4; j++) {
            wmma::store_matrix_sync(&patch[wid][0][0], acc[i][j], 20, wmma::mem_row_major);
            __syncwarp();
            const int r = iw + 16 * i + pr;
            const int c = p0 + pwl + 16 * j + pc;
            uint4 o;
            __nv_bfloat162* op = (__nv_bfloat162*)&o;
#pragma unroll
            for (int t = 0; t < 4; t++)
                op[t] = __floats2bfloat162_rn(patch[wid][pr][pc + 2*t], patch[wid][pr][pc + 2*t + 1]);
            *(uint4*)&Y[(size_t)r * M2 + c] = o;
            __syncwarp();
        }
}

// ---------------------------------------------------------------------------
// Stage 5 (per batch): final linears + residual (fp32 out). grid (16, 2, 2)
// ---------------------------------------------------------------------------
__global__ __launch_bounds__(256, 2) void lin2_tc(
    const float* __restrict__ Qb, const float* __restrict__ det,
    const float* __restrict__ Wb, const float* __restrict__ aim,
    float* __restrict__ out_det, float* __restrict__ out_aim,
    int batch)
{
    extern __shared__ bf16 smem[];
    __shared__ float patch[8][16][20];
    const int z = blockIdx.z;
    const bf16* X = z ? h_naT : h_ndT;
    const bf16* W = z ? h_wW : h_wQ;
    const float* bias = z ? Wb : Qb;
    const float* res  = z ? aim : det;
    float* Y = z ? out_aim : out_det;

    const int tid = threadIdx.x, wid = tid >> 5, lane = tid & 31;
    const int wm = wid & 3, wn = wid >> 2;
    const int m0b = batch * NSEQ + blockIdx.x * 128;
    const int n0 = blockIdx.y * 128;

    FACC acc[2][4];
#pragma unroll
    for (int i = 0; i < 2; i++)
#pragma unroll
        for (int j = 0; j < 4; j++) wmma::fill_fragment(acc[i][j], 0.0f);

    mainloop_h3s<CD / 32>(X + (size_t)m0b * CD, CD, W + (size_t)n0 * CD, CD,
                          smem, smem + 3 * SLAB_H, acc, tid, wm * 32, wn * 64);

    const int m0 = m0b + wm * 32;
    const int n0w = n0 + wn * 64;
    const int pr = lane & 15, pc = (lane >> 4) * 8;
#pragma unroll
    for (int i = 0; i < 2; i++)
#pragma unroll
        for (int j = 0; j < 4; j++) {
            wmma::store_matrix_sync(&patch[wid][0][0], acc[i][j], 20, wmma::mem_row_major);
            __syncwarp();
            const int m = m0 + 16 * i + pr;
            const int nb = n0w + 16 * j + pc;
            const float* rrow = &res[(size_t)m * CD + nb];
            float r[8];
#pragma unroll
            for (int t = 0; t < 8; t++)
                r[t] = patch[wid][pr][pc + t] + bias[nb + t] + rrow[t];
            float* row = &Y[(size_t)m * CD + nb];
            *(float4*)(row)     = make_float4(r[0], r[1], r[2], r[3]);
            *(float4*)(row + 4) = make_float4(r[4], r[5], r[6], r[7]);
            __syncwarp();
        }
}

// ---------------------------------------------------------------------------
extern "C" void kernel_launch(void* const* d_in, const int* in_sizes, int n_in,
                              void* d_out, int out_size)
{
    const float* detect = (const float*)d_in[0];
    const float* aim    = (const float*)d_in[1];
    const float* g_w  = (const float*)d_in[2];  const float* g_b  = (const float*)d_in[3];
    const float* g2_w = (const float*)d_in[4];  const float* g2_b = (const float*)d_in[5];
    const float* th_w = (const float*)d_in[6];  const float* th_b = (const float*)d_in[7];
    const float* ph_w = (const float*)d_in[8];  const float* ph_b = (const float*)d_in[9];
    const float* W_w  = (const float*)d_in[10]; const float* W_b  = (const float*)d_in[11];
    const float* Q_w  = (const float*)d_in[12]; const float* Q_b  = (const float*)d_in[13];

    float* out_det = (float*)d_out;
    float* out_aim = out_det + (size_t)B_ * NSEQ * CD;

    const int smemLin = 6 * SLAB_H * (int)sizeof(bf16);    // 61440
    const int smemOut = 6 * SLAB2_H * (int)sizeof(bf16);   // 52224
    cudaFuncSetAttribute(lin4_tc,      cudaFuncAttributeMaxDynamicSharedMemorySize, smemLin);
    cudaFuncSetAttribute(s_partial_tc, cudaFuncAttributeMaxDynamicSharedMemorySize, smemLin);
    cudaFuncSetAttribute(out_small_tc, cudaFuncAttributeMaxDynamicSharedMemorySize, smemOut);
    cudaFuncSetAttribute(lin2_tc,      cudaFuncAttributeMaxDynamicSharedMemorySize, smemLin);

    // forked-capture per-batch chains: 4 streams + events (host objects only)
    cudaStream_t st[B_];
    cudaEvent_t evRoot, evDone[B_];
    for (int b = 0; b < B_; b++)
        cudaStreamCreateWithFlags(&st[b], cudaStreamNonBlocking);
    cudaEventCreateWithFlags(&evRoot, cudaEventDisableTiming);
    for (int b = 0; b < B_; b++)
        cudaEventCreateWithFlags(&evDone[b], cudaEventDisableTiming);

    // Stage 0 on the captured origin stream
    cvt_kernel<<<dim3(LIN_ELEMS / (256 * 8), 8), 256>>>(
        detect, aim, g_w, g2_w, th_w, ph_w, W_w, Q_w);
    cudaEventRecord(evRoot, 0);

    for (int b = 0; b < B_; b++) {
        cudaStreamWaitEvent(st[b], evRoot, 0);
        lin4_tc<<<dim3(16, 2, 4), 256, smemLin, st[b]>>>(g_b, g2_b, th_b, ph_b, b);
        s_partial_tc<<<dim3(NSPLIT, 2), 256, smemLin, st[b]>>>(b);
        s_reduce_kernel<<<dim3(64, 2), 256, 0, st[b]>>>(b);
        out_small_tc<<<dim3(M2 / 128, 2), 256, smemOut, st[b]>>>(b);
        lin2_tc<<<dim3(16, 2, 2), 256, smemLin, st[b]>>>(
            Q_b, detect, W_b, aim, out_det, out_aim, b);
        cudaEventRecord(evDone[b], st[b]);
    }
    for (int b = 0; b < B_; b++)
        cudaStreamWaitEvent(0, evDone[b], 0);

    for (int b = 0; b < B_; b++) cudaStreamDestroy(st[b]);
    cudaEventDestroy(evRoot);
    for (int b = 0; b < B_; b++) cudaEventDestroy(evDone[b]);
}